// round 3
// baseline (speedup 1.0000x reference)
#include <cuda_runtime.h>

// ImageWarpingLayer: out = bilinear_sample(image, grid + flow)
// image: [B=16, H=512, W=512, C=8] f32   flow: [B, H, W, 2] f32 (dy, dx)
// TF dense_image_warp semantics: floor clamped to [0, size-2],
// alpha = clip(q - floor, 0, 1).
//
// Mapping: work-unit = (pixel, float4-half-of-C). 2 units per thread
// (tid and tid + TOTAL/2), loads front-batched for 2x memory-level
// parallelism. Stores are streaming (.cs) since output is never re-read.

#define Bn 16
#define Hn 512
#define Wn 512
#define Cn 8

#define TOTAL_UNITS (Bn * Hn * Wn * 2)      // 8388608
#define HALF_UNITS  (TOTAL_UNITS / 2)       // 4194304

__global__ __launch_bounds__(256)
void warp_kernel(const float* __restrict__ image,
                 const float* __restrict__ flow,
                 float* __restrict__ out)
{
    const int tid = blockIdx.x * blockDim.x + threadIdx.x;

    int   uid[2];
    uid[0] = tid;
    uid[1] = tid + HALF_UNITS;

    // ---- front-batched flow loads ----
    float2 f[2];
#pragma unroll
    for (int k = 0; k < 2; k++) {
        f[k] = __ldg(reinterpret_cast<const float2*>(flow) + (uid[k] >> 1));
    }

    // ---- address computation ----
    long top[2], bot[2];
    float ax[2], ay[2];
#pragma unroll
    for (int k = 0; k < 2; k++) {
        const int pix  = uid[k] >> 1;
        const int half = uid[k] & 1;
        const int x = pix & (Wn - 1);
        const int y = (pix >> 9) & (Hn - 1);
        const int b = pix >> 18;

        const float qy = (float)y + f[k].x;
        const float qx = (float)x + f[k].y;

        const float fy = fminf(fmaxf(floorf(qy), 0.0f), (float)(Hn - 2));
        const float fx = fminf(fmaxf(floorf(qx), 0.0f), (float)(Wn - 2));
        ay[k] = fminf(fmaxf(qy - fy, 0.0f), 1.0f);
        ax[k] = fminf(fmaxf(qx - fx, 0.0f), 1.0f);

        const int iy = (int)fy;
        const int ix = (int)fx;

        top[k] = (((long)b * Hn + iy) * Wn + ix) * Cn + half * 4;
        bot[k] = top[k] + (long)Wn * Cn;
    }

    // ---- front-batched gathers: 8 independent LDG.128 in flight ----
    float4 tl[2], tr[2], bl[2], br[2];
#pragma unroll
    for (int k = 0; k < 2; k++) {
        tl[k] = __ldg(reinterpret_cast<const float4*>(image + top[k]));
        tr[k] = __ldg(reinterpret_cast<const float4*>(image + top[k] + Cn));
        bl[k] = __ldg(reinterpret_cast<const float4*>(image + bot[k]));
        br[k] = __ldg(reinterpret_cast<const float4*>(image + bot[k] + Cn));
    }

    // ---- interpolate + streaming store ----
#pragma unroll
    for (int k = 0; k < 2; k++) {
        float4 o;
        float t, bo;
        t   = fmaf(ax[k], tr[k].x - tl[k].x, tl[k].x);
        bo  = fmaf(ax[k], br[k].x - bl[k].x, bl[k].x);
        o.x = fmaf(ay[k], bo - t, t);
        t   = fmaf(ax[k], tr[k].y - tl[k].y, tl[k].y);
        bo  = fmaf(ax[k], br[k].y - bl[k].y, bl[k].y);
        o.y = fmaf(ay[k], bo - t, t);
        t   = fmaf(ax[k], tr[k].z - tl[k].z, tl[k].z);
        bo  = fmaf(ax[k], br[k].z - bl[k].z, bl[k].z);
        o.z = fmaf(ay[k], bo - t, t);
        t   = fmaf(ax[k], tr[k].w - tl[k].w, tl[k].w);
        bo  = fmaf(ax[k], br[k].w - bl[k].w, bl[k].w);
        o.w = fmaf(ay[k], bo - t, t);

        __stcs(reinterpret_cast<float4*>(out) + uid[k], o);
    }
}

extern "C" void kernel_launch(void* const* d_in, const int* in_sizes, int n_in,
                              void* d_out, int out_size)
{
    const float* image = (const float*)d_in[0];
    const float* flow  = (const float*)d_in[1];
    float* out = (float*)d_out;

    const int threads = 256;
    const int blocks = HALF_UNITS / threads; // 16384
    warp_kernel<<<blocks, threads>>>(image, flow, out);
}

// round 4
// speedup vs baseline: 1.0609x; 1.0609x over previous
#include <cuda_runtime.h>
#include <cstdint>

// ImageWarpingLayer: out = bilinear_sample(image, grid + flow)
// image: [B=16, H=512, W=512, C=8] f32   flow: [B, H, W, 2] f32 (dy, dx)
// TF dense_image_warp semantics: floor clamped to [0, size-2],
// alpha = clip(q - floor, 0, 1).
//
// Work-unit = (pixel, float4-half-of-C). Warp = 32 consecutive units =
// 16 consecutive pixels (gathers near-contiguous). Output is staged in
// SMEM and written with one 8KB cp.async.bulk (TMA 1D) per block,
// removing store wavefronts from the L1tex pipe (the measured bottleneck).

#define Bn 16
#define Hn 512
#define Wn 512
#define Cn 8

#define UNITS_PER_BLOCK 512             // 2 units per thread, 256 threads
#define TOTAL_UNITS (Bn * Hn * Wn * 2)  // 8388608

__device__ __forceinline__ uint32_t smem_u32(const void* p) {
    uint32_t a;
    asm("{ .reg .u64 t; cvta.to.shared.u64 t, %1; cvt.u32.u64 %0, t; }"
        : "=r"(a) : "l"(p));
    return a;
}

__global__ __launch_bounds__(256)
void warp_kernel(const float* __restrict__ image,
                 const float* __restrict__ flow,
                 float* __restrict__ out)
{
    __shared__ __align__(16) float4 buf[UNITS_PER_BLOCK];  // 8 KB

    const int base = blockIdx.x * UNITS_PER_BLOCK;
    const int t    = threadIdx.x;

#pragma unroll
    for (int k = 0; k < 2; k++) {
        const int slot = t + k * 256;
        const int uid  = base + slot;

        const int pix  = uid >> 1;
        const int half = uid & 1;
        const int x = pix & (Wn - 1);
        const int y = (pix >> 9) & (Hn - 1);
        const int b = pix >> 18;

        const float2 f = __ldg(reinterpret_cast<const float2*>(flow) + pix);
        const float qy = (float)y + f.x;
        const float qx = (float)x + f.y;

        const float fy = fminf(fmaxf(floorf(qy), 0.0f), (float)(Hn - 2));
        const float fx = fminf(fmaxf(floorf(qx), 0.0f), (float)(Wn - 2));
        const float ay = fminf(fmaxf(qy - fy, 0.0f), 1.0f);
        const float ax = fminf(fmaxf(qx - fx, 0.0f), 1.0f);

        const int iy = (int)fy;
        const int ix = (int)fx;

        const long top = (((long)b * Hn + iy) * Wn + ix) * Cn + half * 4;
        const long bot = top + (long)Wn * Cn;

        const float4 tl = __ldg(reinterpret_cast<const float4*>(image + top));
        const float4 tr = __ldg(reinterpret_cast<const float4*>(image + top + Cn));
        const float4 bl = __ldg(reinterpret_cast<const float4*>(image + bot));
        const float4 br = __ldg(reinterpret_cast<const float4*>(image + bot + Cn));

        float4 o;
        float tt, bo;
        tt  = fmaf(ax, tr.x - tl.x, tl.x);
        bo  = fmaf(ax, br.x - bl.x, bl.x);
        o.x = fmaf(ay, bo - tt, tt);
        tt  = fmaf(ax, tr.y - tl.y, tl.y);
        bo  = fmaf(ax, br.y - bl.y, bl.y);
        o.y = fmaf(ay, bo - tt, tt);
        tt  = fmaf(ax, tr.z - tl.z, tl.z);
        bo  = fmaf(ax, br.z - bl.z, bl.z);
        o.z = fmaf(ay, bo - tt, tt);
        tt  = fmaf(ax, tr.w - tl.w, tl.w);
        bo  = fmaf(ax, br.w - bl.w, bl.w);
        o.w = fmaf(ay, bo - tt, tt);

        buf[slot] = o;  // STS.128, conflict-free
    }

    __syncthreads();

    if (t == 0) {
        // Order generic-proxy smem writes before async-proxy read
        asm volatile("fence.proxy.async.shared::cta;" ::: "memory");
        const uint32_t s = smem_u32(buf);
        float* g = out + (long)base * 4;  // 4 floats per unit
        asm volatile(
            "cp.async.bulk.global.shared::cta.bulk_group [%0], [%1], %2;"
            :: "l"(g), "r"(s), "n"(UNITS_PER_BLOCK * 16) : "memory");
        asm volatile("cp.async.bulk.commit_group;" ::: "memory");
        asm volatile("cp.async.bulk.wait_group 0;" ::: "memory");
    }
}

extern "C" void kernel_launch(void* const* d_in, const int* in_sizes, int n_in,
                              void* d_out, int out_size)
{
    const float* image = (const float*)d_in[0];
    const float* flow  = (const float*)d_in[1];
    float* out = (float*)d_out;

    const int blocks = TOTAL_UNITS / UNITS_PER_BLOCK; // 16384
    warp_kernel<<<blocks, 256>>>(image, flow, out);
}